// round 5
// baseline (speedup 1.0000x reference)
#include <cuda_runtime.h>

#define Tlen 1000
#define Bsz  4096
#define INsz 8
#define Hsz  50
#define Osz  6
#define NDIM 56
#define BTILE 32
#define ROWW 68   // row stride in floats for both sW and sV
// Quarter-interleaved row layout (64 logical j -> 64 words):
//   logical j = q*16 + c*4 + e  (q,c in 0..3, e in 0..3)
//   stored word = c*16 + q*4 + e
// j semantics: j<50 -> W_rec/W_out vs relu(h); 50..55 zero pad; 56..63 -> W_in vs x_t

__device__ __forceinline__ void fma2(unsigned long long& acc,
                                     unsigned long long a,
                                     unsigned long long b) {
    asm("fma.rn.f32x2 %0, %1, %2, %0;" : "+l"(acc) : "l"(a), "l"(b));
}

__device__ __forceinline__ float hadd2(unsigned long long a) {
    float lo, hi;
    asm("mov.b64 {%0, %1}, %2;" : "=f"(lo), "=f"(hi) : "l"(a));
    return lo + hi;
}

__device__ __forceinline__ int word_of_j(int j) {
    int q = j >> 4, c = (j >> 2) & 3, e = j & 3;
    return c * 16 + q * 4 + e;
}

__global__ void __launch_bounds__(512, 1) biornn_kernel(
    const float* __restrict__ x,       // (T, B, 8)
    const float* __restrict__ W_in,    // (50, 8)
    const float* __restrict__ W_rec,   // (50, 50)
    const float* __restrict__ bias,    // (50,)
    const float* __restrict__ W_out_w, // (6, 50)
    const float* __restrict__ W_out_b, // (6,)
    float* __restrict__ out)           // (T, B, 6)
{
    __shared__ __align__(16) float sW[NDIM * ROWW];
    __shared__ __align__(16) float sV[2 * BTILE * ROWW];
    __shared__ float sB[NDIM];

    const int tid = threadIdx.x;

    // ---- stage weights into quarter-interleaved rows ----
    for (int i = tid; i < NDIM * ROWW; i += 512) {
        int d = i / ROWW, wi = i - d * ROWW;
        float val = 0.f;
        if (wi < 64) {
            int c = wi >> 4, rem = wi & 15;
            int j = (rem >> 2) * 16 + c * 4 + (rem & 3);
            if (d < Hsz) {
                if (j < Hsz)       val = W_rec[d * Hsz + j];
                else if (j >= 56)  val = W_in[d * INsz + (j - 56)];
            } else {
                if (j < Hsz)       val = W_out_w[(d - Hsz) * Hsz + j];
            }
        }
        sW[i] = val;
    }
    for (int i = tid; i < 2 * BTILE * ROWW; i += 512) sV[i] = 0.f;
    for (int i = tid; i < NDIM; i += 512)
        sB[i] = (i < Hsz) ? bias[i] : W_out_b[i - Hsz];
    __syncthreads();

    const int g = tid >> 6;          // dim group: 7 dims
    const int p = (tid >> 2) & 15;   // batch-pair slot: batches {p, p+16}
    const int q = tid & 3;           // j quarter
    const int gb0 = blockIdx.x * BTILE;
    const bool is_y = (g == 7);      // dims 49..55 (dl0=49 is h-dim)

    float h0[7], h1[7], br[7];
    int wd[7];
    #pragma unroll
    for (int dl = 0; dl < 7; dl++) {
        int d = g * 7 + dl;
        h0[dl] = 0.f; h1[dl] = 0.f;
        br[dl] = sB[d];
        wd[dl] = word_of_j(d);
    }

    const float* wbase = sW + (g * 7) * ROWW + q * 4;

    // ---- x duty: first 64 threads cover 32 batches x 2 float4 ----
    const bool xduty = (tid < 64);
    const int xbat  = tid >> 1;          // 0..31
    const int xhalf = tid & 1;           // float4 index
    float4 xreg;
    const float4* xp = reinterpret_cast<const float4*>(x);
    if (xduty)
        xreg = xp[((size_t)0 * Bsz + gb0 + xbat) * 2 + xhalf];

    #pragma unroll 1
    for (int t = 0; t < Tlen; t++) {
        float* vb  = sV + (t & 1) * (BTILE * ROWW);
        float* vr0 = vb + p * ROWW;
        float* vr1 = vb + (p + 16) * ROWW;

        // ---- publish relu(h): one q-lane per dim ----
        if (!is_y) {
            #pragma unroll
            for (int dl = 0; dl < 7; dl++) {
                if (q == (dl & 3)) {
                    vr0[wd[dl]] = fmaxf(h0[dl], 0.f);
                    vr1[wd[dl]] = fmaxf(h1[dl], 0.f);
                }
            }
        } else {
            if (q == 0) {
                vr0[wd[0]] = fmaxf(h0[0], 0.f);   // dim 49
                vr1[wd[0]] = fmaxf(h1[0], 0.f);
            }
        }

        // ---- publish x_t (words 44..47 / 60..63), prefetch x_{t+1} ----
        if (xduty) {
            float* xr = vb + xbat * ROWW + (44 + 16 * xhalf);
            *reinterpret_cast<float4*>(xr) = xreg;
            if (t + 1 < Tlen)
                xreg = xp[((size_t)(t + 1) * Bsz + gb0 + xbat) * 2 + xhalf];
        }
        __syncthreads();

        // ---- quarter-matvec: 7 dims x 2 batches x 16 j ----
        unsigned long long acc0[7], acc1[7];
        #pragma unroll
        for (int dl = 0; dl < 7; dl++) { acc0[dl] = 0ull; acc1[dl] = 0ull; }

        #pragma unroll
        for (int c = 0; c < 4; c++) {
            ulonglong2 a =
                *reinterpret_cast<const ulonglong2*>(vr0 + c * 16 + q * 4);
            ulonglong2 bch =
                *reinterpret_cast<const ulonglong2*>(vr1 + c * 16 + q * 4);
            #pragma unroll
            for (int dl = 0; dl < 7; dl++) {
                ulonglong2 w = *reinterpret_cast<const ulonglong2*>(
                    wbase + dl * ROWW + c * 16);
                fma2(acc0[dl], a.x,   w.x);
                fma2(acc0[dl], a.y,   w.y);
                fma2(acc1[dl], bch.x, w.x);
                fma2(acc1[dl], bch.y, w.y);
            }
        }

        // ---- butterfly-combine quarters; finalize ----
        size_t ob0 = ((size_t)t * Bsz + gb0 + p) * Osz;
        size_t ob1 = ((size_t)t * Bsz + gb0 + p + 16) * Osz;
        #pragma unroll
        for (int dl = 0; dl < 7; dl++) {
            float s0 = hadd2(acc0[dl]);
            float s1 = hadd2(acc1[dl]);
            s0 += __shfl_xor_sync(0xffffffffu, s0, 1);
            s0 += __shfl_xor_sync(0xffffffffu, s0, 2);
            s1 += __shfl_xor_sync(0xffffffffu, s1, 1);
            s1 += __shfl_xor_sync(0xffffffffu, s1, 2);
            float so0 = s0 + br[dl];
            float so1 = s1 + br[dl];
            if (!is_y || dl == 0) {
                h0[dl] = fmaf(0.1f, so0 - h0[dl], h0[dl]);
                h1[dl] = fmaf(0.1f, so1 - h1[dl], h1[dl]);
            } else {
                if (q == ((dl - 1) & 3)) {
                    out[ob0 + (dl - 1)] = so0;
                    out[ob1 + (dl - 1)] = so1;
                }
            }
        }
    }
}

extern "C" void kernel_launch(void* const* d_in, const int* in_sizes, int n_in,
                              void* d_out, int out_size) {
    const float* x        = (const float*)d_in[0];
    const float* W_in     = (const float*)d_in[1];
    const float* W_rec    = (const float*)d_in[2];
    const float* bias     = (const float*)d_in[3];
    const float* W_out_w  = (const float*)d_in[4];
    const float* W_out_b  = (const float*)d_in[5];
    float* out = (float*)d_out;

    biornn_kernel<<<Bsz / BTILE, 512>>>(x, W_in, W_rec, bias,
                                        W_out_w, W_out_b, out);
}